// round 17
// baseline (speedup 1.0000x reference)
#include <cuda_runtime.h>
#include <cuda_fp16.h>
#include <cstdint>

#define TOK   32768
#define DIN   1024
#define RDIM  128
#define NSLOT 4096
#define MAXK  32
#define KSEL  48

typedef unsigned long long u64;

// ---------------- scratch ----------------
__device__ float    g_hidden[TOK * RDIM];
__device__ __half2  g_scores_h2[TOK * NSLOT / 2];   // 256 MB approx scores (fp16)
__device__ float    g_wsT[NSLOT * RDIM];            // 2 MB W_s transposed (fp32, refine)
__device__ unsigned g_wsHp[64 * NSLOT];             // 1 MB W_s fp16 k-pair packed
__device__ int      g_budget[TOK];
__device__ float4   g_counts_v[NSLOT / 4];
__device__ float    g_aux;

#define g_scores_h ((__half*)g_scores_h2)
#define g_counts   ((float*)g_counts_v)

// ---------------- fp16 MMA ----------------
#define MMA_F16(c, a, b) \
    asm volatile("mma.sync.aligned.m16n8k16.row.col.f32.f16.f16.f32 " \
        "{%0,%1,%2,%3}, {%4,%5,%6,%7}, {%8,%9}, {%0,%1,%2,%3};" \
        : "+f"((c)[0]), "+f"((c)[1]), "+f"((c)[2]), "+f"((c)[3]) \
        : "r"((a)[0]), "r"((a)[1]), "r"((a)[2]), "r"((a)[3]), \
          "r"((b)[0]), "r"((b)[1]))

// smem: sA frag 32 KB | sB half2[64][72] 18 KB | sC half2[128][36] 18 KB
#define BSTR2     72
#define CSTR      36
#define SM2_A     0
#define SM2_B     32768
#define SM2_C     (32768 + 64 * BSTR2 * 4)
#define SM2_TOTAL (SM2_C + 128 * CSTR * 4)     // 69632

// 16-bit sortable key for fp16 bits
__device__ __forceinline__ unsigned key16(unsigned h) {
    unsigned m = ((h >> 15) & 1u) ? 0xFFFFu : 0x8000u;
    return (h ^ m) & 0xFFFFu;
}

// ---------------- reductions ----------------
__device__ __forceinline__ float warpReduceMaxF(float v) {
#pragma unroll
    for (int o = 16; o > 0; o >>= 1) v = fmaxf(v, __shfl_xor_sync(0xffffffffu, v, o));
    return v;
}
__device__ __forceinline__ float warpReduceSumF(float v) {
#pragma unroll
    for (int o = 16; o > 0; o >>= 1) v += __shfl_xor_sync(0xffffffffu, v, o);
    return v;
}
__device__ __forceinline__ int warpReduceSumI(int v) {
#pragma unroll
    for (int o = 16; o > 0; o >>= 1) v += __shfl_xor_sync(0xffffffffu, v, o);
    return v;
}
__device__ __forceinline__ int warpReduceMinI(int v) {
#pragma unroll
    for (int o = 16; o > 0; o >>= 1) {
        int t = __shfl_xor_sync(0xffffffffu, v, o);
        v = (t < v) ? t : v;
    }
    return v;
}
__device__ __forceinline__ u64 warpReduceMaxU64(u64 v) {
#pragma unroll
    for (int o = 16; o > 0; o >>= 1) {
        u64 t = __shfl_xor_sync(0xffffffffu, v, o);
        v = (t > v) ? t : v;
    }
    return v;
}

// ---------------- K0 ----------------
__global__ void k_init() {
    int i = blockIdx.x * blockDim.x + threadIdx.x;
    if (i < NSLOT) g_counts[i] = 0.f;
    if (i == 0)    g_aux = 0.f;
}

// ---------------- K0b: prep W_s -> g_wsT (fp32 [N][R]) + g_wsHp (fp16 k-pairs) ----------------
__global__ __launch_bounds__(256) void k_prep(const float* __restrict__ Wsg) {
    __shared__ float tile[32][33];
    const int bx = blockIdx.x;
    const int by = blockIdx.y;
    const int tx = threadIdx.x & 31, ty = threadIdx.x >> 5;
#pragma unroll
    for (int i = 0; i < 4; i++) {
        int r = by * 32 + ty + i * 8;
        tile[ty + i * 8][tx] = Wsg[(size_t)r * NSLOT + bx * 32 + tx];
    }
    __syncthreads();
#pragma unroll
    for (int i = 0; i < 4; i++) {
        int n = bx * 32 + ty + i * 8;
        g_wsT[(size_t)n * RDIM + by * 32 + tx] = tile[tx][ty + i * 8];
    }
#pragma unroll
    for (int i = 0; i < 2; i++) {
        int id = threadIdx.x + i * 256;
        int rr2 = id >> 5, c = id & 31;
        __half2 p = __halves2half2(__float2half_rn(tile[rr2 * 2][c]),
                                   __float2half_rn(tile[rr2 * 2 + 1][c]));
        g_wsHp[(size_t)(by * 16 + rr2) * NSLOT + bx * 32 + c] = *(unsigned*)&p;
    }
}

// ---------------- K1: hidden GEMM + budget (unchanged) ----------------
__global__ __launch_bounds__(256) void k_hidden(
    const float* __restrict__ x,  const float* __restrict__ Wc, const float* __restrict__ bc,
    const float* __restrict__ Wh, const float* __restrict__ bh, float* __restrict__ out_b)
{
    __shared__ float Xs[32][132];
    __shared__ float Wsm[32][128];
    __shared__ float Wcs[32];

    const int tid = threadIdx.x;
    const int tx = tid & 15, ty = tid >> 4;
    const int t0 = blockIdx.x * 128;

    float acc[8][8];
#pragma unroll
    for (int j = 0; j < 8; j++) {
        int c = (j < 4) ? tx * 4 + j : 64 + tx * 4 + (j - 4);
        float b = bh[c];
#pragma unroll
        for (int i = 0; i < 8; i++) acc[i][j] = b;
    }
    float cacc = 0.f;

    for (int kt = 0; kt < 32; kt++) {
#pragma unroll
        for (int i = 0; i < 4; i++) {
            int id = tid + i * 256;
            int token = id >> 3, kg = id & 7;
            float4 f = *(const float4*)(x + (size_t)(t0 + token) * DIN + kt * 32 + kg * 4);
            Xs[kg * 4 + 0][token] = f.x; Xs[kg * 4 + 1][token] = f.y;
            Xs[kg * 4 + 2][token] = f.z; Xs[kg * 4 + 3][token] = f.w;
        }
#pragma unroll
        for (int i = 0; i < 4; i++) {
            int id = tid + i * 256;
            int rowk = id >> 5, ng = id & 31;
            *(float4*)&Wsm[rowk][ng * 4] =
                *(const float4*)(Wh + (size_t)(kt * 32 + rowk) * RDIM + ng * 4);
        }
        if (tid < 32) Wcs[tid] = Wc[kt * 32 + tid];
        __syncthreads();

#pragma unroll
        for (int k = 0; k < 32; k++) {
            float4 a0 = *(float4*)&Xs[k][ty * 4];
            float4 a1 = *(float4*)&Xs[k][64 + ty * 4];
            float4 b0 = *(float4*)&Wsm[k][tx * 4];
            float4 b1 = *(float4*)&Wsm[k][64 + tx * 4];
            float xf[8] = {a0.x, a0.y, a0.z, a0.w, a1.x, a1.y, a1.z, a1.w};
            float wf[8] = {b0.x, b0.y, b0.z, b0.w, b1.x, b1.y, b1.z, b1.w};
#pragma unroll
            for (int i = 0; i < 8; i++)
#pragma unroll
                for (int j = 0; j < 8; j++)
                    acc[i][j] += xf[i] * wf[j];
        }
        if (tid < 128) {
            float s = 0.f;
#pragma unroll
            for (int k = 0; k < 32; k++) s += Xs[k][tid] * Wcs[k];
            cacc += s;
        }
        __syncthreads();
    }

#pragma unroll
    for (int i = 0; i < 8; i++) {
        int r = (i < 4) ? ty * 4 + i : 64 + ty * 4 + (i - 4);
        float4 o0 = make_float4(fmaxf(acc[i][0], 0.f), fmaxf(acc[i][1], 0.f),
                                fmaxf(acc[i][2], 0.f), fmaxf(acc[i][3], 0.f));
        float4 o1 = make_float4(fmaxf(acc[i][4], 0.f), fmaxf(acc[i][5], 0.f),
                                fmaxf(acc[i][6], 0.f), fmaxf(acc[i][7], 0.f));
        *(float4*)(g_hidden + (size_t)(t0 + r) * RDIM + tx * 4) = o0;
        *(float4*)(g_hidden + (size_t)(t0 + r) * RDIM + 64 + tx * 4) = o1;
    }
    if (tid < 128) {
        float zc = cacc + bc[0];
        float c = 1.f / (1.f + expf(-zc));
        float bf = 4.f + 28.f * c * c;
        int b = (int)floorf(bf);
        g_budget[t0 + tid] = b;
        out_b[t0 + tid] = (float)b;
    }
}

// ---------------- K2: approx scores via fp16 mma.sync m16n8k16 (unchanged) ----------------
__global__ __launch_bounds__(256, 2) void k_scores_mma(const float* __restrict__ bs)
{
    extern __shared__ char smem[];
    unsigned* sA = (unsigned*)(smem + SM2_A);
    unsigned* sB = (unsigned*)(smem + SM2_B);
    unsigned* sC = (unsigned*)(smem + SM2_C);
    const uint4* sA4 = (const uint4*)sA;

    const int tid = threadIdx.x;
    const int lane = tid & 31, wid = tid >> 5;
    const int warpM = wid & 3, warpN = wid >> 2;
    const int gid = lane >> 2, tig = lane & 3;
    const int t0 = blockIdx.x * 128;

#pragma unroll
    for (int i = 0; i < 16; i++) {
        int id = tid + i * 256;
        int m = id >> 5, fg = id & 31;
        float4 v = *(const float4*)(g_hidden + (size_t)(t0 + m) * RDIM + fg * 4);
        __half2 h01 = __floats2half2_rn(v.x, v.y);
        __half2 h23 = __floats2half2_rn(v.z, v.w);
        int mt = m >> 4, rr = m & 15;
        int kc = fg >> 2;
        int j0 = (fg & 3) * 2;
        int khi = j0 >> 2;
        int base = ((mt * 8 + kc) * 32 + (rr & 7) * 4);
        int regbase = (rr >> 3) | (khi << 1);
        sA[(base + (j0 & 3)) * 4 + regbase]       = *(unsigned*)&h01;
        sA[(base + ((j0 + 1) & 3)) * 4 + regbase] = *(unsigned*)&h23;
    }

    {
        uint4 pre[4];
#pragma unroll
        for (int i = 0; i < 4; i++) {
            int id = tid + i * 256;
            int rp = id >> 4, ng = id & 15;
            pre[i] = *(const uint4*)(g_wsHp + (size_t)rp * NSLOT + ng * 4);
        }
#pragma unroll
        for (int i = 0; i < 4; i++) {
            int id = tid + i * 256;
            int rp = id >> 4, ng = id & 15;
            *(uint4*)&sB[rp * BSTR2 + ng * 4] = pre[i];
        }
    }
    __syncthreads();

    for (int nt = 0; nt < 64; nt++) {
        const int nbase = nt * 64;

        uint4 pre[4];
        if (nt < 63) {
#pragma unroll
            for (int i = 0; i < 4; i++) {
                int id = tid + i * 256;
                int rp = id >> 4, ng = id & 15;
                pre[i] = *(const uint4*)(g_wsHp + (size_t)rp * NSLOT + nbase + 64 + ng * 4);
            }
        }

        float c[2][4][4];
#pragma unroll
        for (int mi = 0; mi < 2; mi++)
#pragma unroll
            for (int ni = 0; ni < 4; ni++)
#pragma unroll
                for (int q = 0; q < 4; q++) c[mi][ni][q] = 0.f;

        const int colB = warpN * 32 + gid;

#pragma unroll
        for (int kc = 0; kc < 8; kc++) {
            uint4 af[2];
#pragma unroll
            for (int mi = 0; mi < 2; mi++)
                af[mi] = sA4[((warpM * 2 + mi) * 8 + kc) * 32 + lane];

            unsigned bf[4][2];
            const unsigned* bR0 = sB + (kc * 8 + tig) * BSTR2 + colB;
            const unsigned* bR1 = bR0 + 4 * BSTR2;
#pragma unroll
            for (int ni = 0; ni < 4; ni++) {
                bf[ni][0] = bR0[ni * 8];
                bf[ni][1] = bR1[ni * 8];
            }
#pragma unroll
            for (int mi = 0; mi < 2; mi++)
#pragma unroll
                for (int ni = 0; ni < 4; ni++)
                    MMA_F16(c[mi][ni], (const unsigned*)&af[mi], bf[ni]);
        }

#pragma unroll
        for (int mi = 0; mi < 2; mi++) {
            int row = warpM * 32 + mi * 16 + gid;
#pragma unroll
            for (int ni = 0; ni < 4; ni++) {
                int col = nbase + warpN * 32 + ni * 8 + tig * 2;
                float2 bb = *(const float2*)(bs + col);
                __half2 lo = __floats2half2_rn(c[mi][ni][0] + bb.x, c[mi][ni][1] + bb.y);
                __half2 hi = __floats2half2_rn(c[mi][ni][2] + bb.x, c[mi][ni][3] + bb.y);
                int cw = warpN * 16 + ni * 4 + tig;
                sC[row * CSTR + cw]       = *(unsigned*)&lo;
                sC[(row + 8) * CSTR + cw] = *(unsigned*)&hi;
            }
        }

        __syncthreads();

#pragma unroll
        for (int q = 0; q < 4; q++) {
            int id = tid + q * 256;
            int row = id >> 3, c16 = id & 7;
            uint4 v = *(const uint4*)&sC[row * CSTR + c16 * 4];
            *(uint4*)(g_scores_h + (size_t)(t0 + row) * NSLOT + nbase + c16 * 8) = v;
        }
        if (nt < 63) {
#pragma unroll
            for (int i = 0; i < 4; i++) {
                int id = tid + i * 256;
                int rp = id >> 4, ng = id & 15;
                *(uint4*)&sB[rp * BSTR2 + ng * 4] = pre[i];
            }
        }
        __syncthreads();
    }
}

// ---------------- K3: register-resident keys + exact refine ----------------
__global__ __launch_bounds__(128) void k_topk(float* __restrict__ out_idx,
                                              float* __restrict__ out_w,
                                              const float* __restrict__ bsg)
{
    __shared__ u64      cand[256];
    __shared__ float    hrow[128];
    __shared__ float    fred[4], f2red[4];
    __shared__ int      ired[4];
    __shared__ unsigned s_cnt;
    __shared__ int      s_best;

    const int t = blockIdx.x;
    const int tid = threadIdx.x, lane = tid & 31, wid = tid >> 5;
    const uint4* rowv = (const uint4*)(g_scores_h + (size_t)t * NSLOT);

    if (tid < 32)
        *(float4*)&hrow[tid * 4] = *(const float4*)(g_hidden + (size_t)t * RDIM + tid * 4);

    // load 32 fp16 values/thread -> 16 packed 16-bit keys in REGISTERS + stats
    unsigned pk[16];
    float s = 0.f, s2 = 0.f;
#pragma unroll
    for (int i = 0; i < 4; i++) {
        uint4 v = rowv[tid + i * 128];
        unsigned w[4] = {v.x, v.y, v.z, v.w};
#pragma unroll
        for (int j = 0; j < 4; j++) {
            float2 f2 = __half22float2(*(__half2*)&w[j]);
            s += f2.x + f2.y;
            s2 += f2.x * f2.x + f2.y * f2.y;
            pk[i * 4 + j] = key16(w[j] & 0xFFFFu) | (key16(w[j] >> 16) << 16);
        }
    }
    s = warpReduceSumF(s);
    s2 = warpReduceSumF(s2);
    if (lane == 0) { fred[wid] = s; f2red[wid] = s2; }
    __syncthreads();
    float ss = 0.f, ss2 = 0.f;
#pragma unroll
    for (int i = 0; i < 4; i++) { ss += fred[i]; ss2 += f2red[i]; }
    const float mean = ss * (1.f / NSLOT);
    const float sigma = sqrtf(fmaxf(ss2 * (1.f / NSLOT) - mean * mean, 0.f)) + 1e-20f;

    // counting over REGISTER keys (no LDS)
    auto countGreater = [&](unsigned tk) -> int {
        int c = 0;
#pragma unroll
        for (int q = 0; q < 16; q++)
            c += ((pk[q] & 0xFFFFu) > tk) + ((pk[q] >> 16) > tk);
        c = warpReduceSumI(c);
        __syncthreads();
        if (lane == 0) ired[wid] = c;
        __syncthreads();
        int tot = 0;
#pragma unroll
        for (int i = 0; i < 4; i++) tot += ired[i];
        return tot;
    };

    unsigned thrKey = 0;
    int cnt = 0;
    bool ok = false;
    float zf = 2.05f;
    for (int a = 0; a < 4; a++) {
        __half th = __float2half_rn(mean + zf * sigma);
        unsigned tk = key16((unsigned)__half_as_ushort(th));
        int c = countGreater(tk);
        if (c >= KSEL && c <= 256) { thrKey = tk; cnt = c; ok = true; break; }
        zf += (c < KSEL) ? -0.55f : 0.45f;
    }

    bool tiePath = false;
    unsigned Tkey = 0;
    if (!ok) {
        unsigned K = 0;
        for (int bit = 15; bit >= 0; bit--) {
            unsigned trial = K | (1u << bit);
            if (countGreater(trial) >= KSEL) K = trial;
        }
        int c = countGreater(K);
        if (c <= 256) {
            thrKey = K; cnt = c; ok = true;
        } else {
            tiePath = true;
            Tkey = K + 1u;
            thrKey = Tkey;
            cnt = countGreater(Tkey);
        }
    }

    // compaction from registers
    if (tid == 0) s_cnt = 0;
    __syncthreads();
    {
        unsigned my = 0;
#pragma unroll
        for (int q = 0; q < 16; q++)
            my += ((pk[q] & 0xFFFFu) > thrKey) + ((pk[q] >> 16) > thrKey);
        unsigned pre = my;
#pragma unroll
        for (int o = 1; o < 32; o <<= 1) {
            unsigned tt = __shfl_up_sync(0xffffffffu, pre, o);
            if (lane >= o) pre += tt;
        }
        unsigned wtot = __shfl_sync(0xffffffffu, pre, 31);
        unsigned wbase = 0;
        if (lane == 31 && wtot > 0) wbase = atomicAdd(&s_cnt, wtot);
        wbase = __shfl_sync(0xffffffffu, wbase, 31);
        unsigned pos = wbase + pre - my;
        if (my > 0) {
#pragma unroll
            for (int q = 0; q < 16; q++) {
                unsigned lo = pk[q] & 0xFFFFu, hi = pk[q] >> 16;
                int idx0 = (tid + (q >> 2) * 128) * 8 + (q & 3) * 2;
                if (lo > thrKey) {
                    if (pos < 256)
                        cand[pos] = ((u64)lo << 12) | (u64)(4095u - (unsigned)idx0);
                    pos++;
                }
                if (hi > thrKey) {
                    if (pos < 256)
                        cand[pos] = ((u64)hi << 12) | (u64)(4095u - (unsigned)(idx0 + 1));
                    pos++;
                }
            }
        }
    }
    __syncthreads();

    if (tiePath) {
        int lastIdx = -1;
        for (int e = cnt; e < KSEL; e++) {
            int best = 0x7FFFFFFF;
#pragma unroll
            for (int q = 0; q < 16; q++) {
                unsigned lo = pk[q] & 0xFFFFu, hi = pk[q] >> 16;
                int idx0 = (tid + (q >> 2) * 128) * 8 + (q & 3) * 2;
                if (lo == Tkey && idx0 > lastIdx && idx0 < best) best = idx0;
                if (hi == Tkey && idx0 + 1 > lastIdx && idx0 + 1 < best) best = idx0 + 1;
            }
            best = warpReduceMinI(best);
            __syncthreads();
            if (lane == 0) ired[wid] = best;
            __syncthreads();
            if (tid == 0) {
                int bb = ired[0];
#pragma unroll
                for (int i = 1; i < 4; i++) bb = (ired[i] < bb) ? ired[i] : bb;
                s_best = bb;
                cand[e] = ((u64)Tkey << 12) | (u64)(4095u - (unsigned)bb);
            }
            __syncthreads();
            lastIdx = s_best;
        }
        cnt = KSEL;
        __syncthreads();
    }

    // exact refine: bias-first, k-serial fmaf (R1 arithmetic)
    const int ncand = (cnt < 256) ? cnt : 256;
    for (int j = tid; j < ncand; j += 128) {
        unsigned idxv = 4095u - (unsigned)(cand[j] & 0xFFFull);
        const float4* wv = (const float4*)(g_wsT + (size_t)idxv * RDIM);
        float acc = __ldg(bsg + idxv);
#pragma unroll
        for (int q = 0; q < 32; q++) {
            float4 w4 = __ldg(wv + q);
            float4 h4 = *(const float4*)&hrow[q * 4];
            acc = fmaf(h4.x, w4.x, acc);
            acc = fmaf(h4.y, w4.y, acc);
            acc = fmaf(h4.z, w4.z, acc);
            acc = fmaf(h4.w, w4.w, acc);
        }
        unsigned b = __float_as_uint(acc);
        unsigned k = b ^ ((unsigned)((int)b >> 31) | 0x80000000u);
        cand[j] = ((u64)k << 12) | (u64)(4095u - idxv);
    }
    __syncthreads();

    // warp 0: exact top-32 extraction + outputs
    if (wid == 0) {
        u64 cl[8];
#pragma unroll
        for (int q = 0; q < 8; q++) {
            int p = lane + 32 * q;
            cl[q] = (p < ncand) ? cand[p] : 0ull;
        }
#pragma unroll
        for (int a = 1; a < 8; a++)
#pragma unroll
            for (int b2 = a; b2 > 0; b2--) {
                u64 lo = cl[b2 - 1] < cl[b2] ? cl[b2 - 1] : cl[b2];
                u64 hi = cl[b2 - 1] < cl[b2] ? cl[b2] : cl[b2 - 1];
                cl[b2 - 1] = hi; cl[b2] = lo;
            }
        u64 mysel = 0;
#pragma unroll
        for (int r2 = 0; r2 < MAXK; r2++) {
            u64 wb = warpReduceMaxU64(cl[0]);
            if (cl[0] == wb) {
#pragma unroll
                for (int q = 0; q < 7; q++) cl[q] = cl[q + 1];
                cl[7] = 0ull;
            }
            if (lane == r2) mysel = wb;
        }

        unsigned keyv = (unsigned)(mysel >> 12);
        unsigned idxv = 4095u - (unsigned)(mysel & 0xFFFull);
        unsigned fb = (keyv & 0x80000000u) ? (keyv ^ 0x80000000u) : ~keyv;
        float val = __uint_as_float(fb);

        int b = g_budget[t];
        float v0 = __shfl_sync(0xffffffffu, val, 0);
        bool msk = lane < b;
        float ev = msk ? __expf(val - v0) : 0.f;
        float zz = warpReduceSumF(ev);
        float w = msk ? ev / zz : 0.f;

        out_idx[(size_t)t * MAXK + lane] = (float)idxv;
        out_w[(size_t)t * MAXK + lane] = w;
        if (msk) atomicAdd(&g_counts[idxv], 1.0f);
    }
}

// ---------------- K4: aux (fp16 approx scores, unchanged) ----------------
__global__ __launch_bounds__(256) void k_aux()
{
    __shared__ float sredZ[8], sredD[8], s_m;
    const int t = blockIdx.x;
    const int tid = threadIdx.x, lane = tid & 31, wid = tid >> 5;
    const uint4* rowv = (const uint4*)(g_scores_h + (size_t)t * NSLOT);

    float fv[16];
    float m = -1e30f;
#pragma unroll
    for (int i = 0; i < 2; i++) {
        uint4 v = rowv[tid + i * 256];
        unsigned w[4] = {v.x, v.y, v.z, v.w};
#pragma unroll
        for (int j = 0; j < 4; j++) {
            float2 f2 = __half22float2(*(__half2*)&w[j]);
            fv[i * 8 + j * 2 + 0] = f2.x;
            fv[i * 8 + j * 2 + 1] = f2.y;
            m = fmaxf(m, fmaxf(f2.x, f2.y));
        }
    }
    m = warpReduceMaxF(m);
    if (lane == 0) sredZ[wid] = m;
    __syncthreads();
    if (tid == 0) {
        float mm = sredZ[0];
#pragma unroll
        for (int i = 1; i < 8; i++) mm = fmaxf(mm, sredZ[i]);
        s_m = mm;
    }
    __syncthreads();
    m = s_m;

    float z = 0.f, d = 0.f;
#pragma unroll
    for (int i = 0; i < 2; i++) {
#pragma unroll
        for (int j = 0; j < 2; j++) {
            float4 c = g_counts_v[(tid + i * 256) * 2 + j];
            float e0 = __expf(fv[i * 8 + j * 4 + 0] - m);
            float e1 = __expf(fv[i * 8 + j * 4 + 1] - m);
            float e2 = __expf(fv[i * 8 + j * 4 + 2] - m);
            float e3 = __expf(fv[i * 8 + j * 4 + 3] - m);
            z += e0 + e1 + e2 + e3;
            d += e0 * c.x + e1 * c.y + e2 * c.z + e3 * c.w;
        }
    }
    z = warpReduceSumF(z);
    d = warpReduceSumF(d);
    if (lane == 0) { sredZ[wid] = z; sredD[wid] = d; }
    __syncthreads();
    if (tid == 0) {
        float zz = 0.f, dd = 0.f;
#pragma unroll
        for (int i = 0; i < 8; i++) { zz += sredZ[i]; dd += sredD[i]; }
        float contrib = (dd / zz) * ((float)NSLOT / ((float)TOK * (float)TOK));
        atomicAdd(&g_aux, contrib);
    }
}

// ---------------- K5 ----------------
__global__ void k_finish(float* __restrict__ out_aux)
{
    if (threadIdx.x == 0) out_aux[0] = g_aux;
}

// ---------------- launch ----------------
extern "C" void kernel_launch(void* const* d_in, const int* in_sizes, int n_in,
                              void* d_out, int out_size)
{
    const float* x  = (const float*)d_in[0];
    const float* Wc = (const float*)d_in[1];
    const float* bc = (const float*)d_in[2];
    const float* Wh = (const float*)d_in[3];
    const float* bh = (const float*)d_in[4];
    const float* Ws = (const float*)d_in[5];
    const float* bs = (const float*)d_in[6];

    float* out     = (float*)d_out;
    float* out_idx = out;
    float* out_w   = out + TOK * MAXK;
    float* out_b   = out + 2 * TOK * MAXK;
    float* out_aux = out + 2 * TOK * MAXK + TOK;

    cudaFuncSetAttribute(k_scores_mma, cudaFuncAttributeMaxDynamicSharedMemorySize, SM2_TOTAL);

    k_init<<<(NSLOT + 255) / 256, 256>>>();
    k_prep<<<dim3(128, 4), 256>>>(Ws);
    k_hidden<<<TOK / 128, 256>>>(x, Wc, bc, Wh, bh, out_b);
    k_scores_mma<<<TOK / 128, 256, SM2_TOTAL>>>(bs);
    k_topk<<<TOK, 128>>>(out_idx, out_w, bs);
    k_aux<<<TOK, 256>>>();
    k_finish<<<1, 32>>>(out_aux);
}